// round 1
// baseline (speedup 1.0000x reference)
#include <cuda_runtime.h>
#include <cuda_bf16.h>

// XLSTM social pooling:
// h_last = hidden[:, :, -1, :]  (N=256, B=64, H=128)
// p_last = pos[:, :, -1, :]     (N=256, B=64, 2)
// mask[i,j,b] = (||p_i - p_j|| <= r) && (i != j)
// out[i,b,:] = sum_j mask * h_last[j,b,:] / max(count, 1)
//
// Design: 2 blocks per batch (grid=128), each block stages the full per-batch
// h tile (256 x 128 fp32 = 128 KB) in shared memory plus the 256 positions.
// Each warp owns one agent i at a time; lanes evaluate 32 distances per
// ballot round (mask is warp-uniform in i), then iterate set bits and
// accumulate the neighbor row (one LDS.128 + 4 FFMA per lane per neighbor).

#define NA   256
#define NB   64
#define SEQL 20
#define HID  128

#define I_PER_BLOCK 128          // 2 blocks per batch
#define THREADS     512          // 16 warps -> 8 agents per warp
#define SMEM_BYTES  (NA * HID * 4 + NA * 8)

__global__ __launch_bounds__(THREADS, 1)
void social_pool_kernel(const float* __restrict__ hidden,
                        const float* __restrict__ pos,
                        const float* __restrict__ radius_ptr,
                        float* __restrict__ out)
{
    extern __shared__ float smem[];
    float*  hs = smem;                          // [256][128]
    float2* ps = (float2*)(smem + NA * HID);    // [256]

    const int b     = blockIdx.x >> 1;
    const int ihalf = blockIdx.x & 1;

    // --- stage positions for this batch (last timestep) ---
    for (int j = threadIdx.x; j < NA; j += THREADS) {
        const float* pp = pos + ((size_t)(j * NB + b) * SEQL + (SEQL - 1)) * 2;
        ps[j] = make_float2(pp[0], pp[1]);
    }

    // --- stage h_last tile [256][128] for this batch (float4 loads) ---
    // t -> row j = t>>5, chunk c = t&31 ; smem offset j*128 + c*4 matches t*4
    #pragma unroll 4
    for (int t = threadIdx.x; t < NA * (HID / 4); t += THREADS) {
        const int j = t >> 5;
        const int c = t & 31;
        const float4* src =
            (const float4*)(hidden + ((size_t)(j * NB + b) * SEQL + (SEQL - 1)) * HID) + c;
        ((float4*)hs)[t] = *src;
    }
    __syncthreads();

    const float r  = *radius_ptr;
    const float r2 = r * r;

    const int warp = threadIdx.x >> 5;
    const int lane = threadIdx.x & 31;

    for (int ii = warp; ii < I_PER_BLOCK; ii += (THREADS / 32)) {
        const int i = ihalf * I_PER_BLOCK + ii;
        const float2 pi = ps[i];

        float4 acc = make_float4(0.f, 0.f, 0.f, 0.f);
        int cnt = 0;

        #pragma unroll
        for (int jb = 0; jb < NA; jb += 32) {
            const int j = jb + lane;
            const float2 pj = ps[j];
            const float dx = pi.x - pj.x;
            const float dy = pi.y - pj.y;
            const bool ok = (dx * dx + dy * dy <= r2) && (j != i);
            unsigned m = __ballot_sync(0xffffffffu, ok);
            cnt += __popc(m);
            while (m) {
                const int bit = __ffs(m) - 1;
                m &= m - 1;
                const float4 hv = ((const float4*)(hs + (jb + bit) * HID))[lane];
                acc.x += hv.x; acc.y += hv.y; acc.z += hv.z; acc.w += hv.w;
            }
        }

        const float scale = 1.0f / fmaxf((float)cnt, 1.0f);
        float4 o;
        o.x = acc.x * scale; o.y = acc.y * scale;
        o.z = acc.z * scale; o.w = acc.w * scale;
        ((float4*)(out + ((size_t)i * NB + b) * HID))[lane] = o;
    }
}

extern "C" void kernel_launch(void* const* d_in, const int* in_sizes, int n_in,
                              void* d_out, int out_size)
{
    const float* hidden = (const float*)d_in[0];   // (256,64,20,128) f32
    const float* pos    = (const float*)d_in[1];   // (256,64,20,2)  f32
    const float* radius = (const float*)d_in[2];   // scalar f32
    float* out = (float*)d_out;                    // (256,64,128)   f32

    cudaFuncSetAttribute(social_pool_kernel,
                         cudaFuncAttributeMaxDynamicSharedMemorySize,
                         SMEM_BYTES);

    social_pool_kernel<<<NB * 2, THREADS, SMEM_BYTES>>>(hidden, pos, radius, out);
}

// round 2
// speedup vs baseline: 1.2569x; 1.2569x over previous
#include <cuda_runtime.h>
#include <cuda_bf16.h>
#include <cstdint>

// XLSTM social pooling (N=256 agents, B=64, H=128, last timestep only):
// out[i,b,:] = mean over j!=i with ||p_i-p_j||<=r of h_last[j,b,:]
//
// R2 changes vs R1 (18.9us, latency-bound: occ 23%, issue 37%):
//  - 1024 threads/block (32 warps/SM instead of 16) -> hide LDS latency
//  - packed add.rn.f32x2 accumulate (2 instr/neighbor instead of 4 FFMA)
//  - 1-deep software pipeline in the neighbor bit loop (prefetch next row)

#define NA   256
#define NB   64
#define SEQL 20
#define HID  128

#define I_PER_BLOCK 128          // 2 blocks per batch
#define THREADS     1024         // 32 warps -> 4 agents per warp
#define NWARPS      (THREADS / 32)
#define SMEM_BYTES  (NA * HID * 4 + NA * 8)

__device__ __forceinline__ void addx2(unsigned long long& acc, unsigned long long v) {
    asm("add.rn.f32x2 %0, %1, %2;" : "=l"(acc) : "l"(acc), "l"(v));
}

__global__ __launch_bounds__(THREADS, 1)
void social_pool_kernel(const float* __restrict__ hidden,
                        const float* __restrict__ pos,
                        const float* __restrict__ radius_ptr,
                        float* __restrict__ out)
{
    extern __shared__ float smem[];
    float*  hs = smem;                          // [256][128] f32
    float2* ps = (float2*)(smem + NA * HID);    // [256]

    const int b     = blockIdx.x >> 1;
    const int ihalf = blockIdx.x & 1;

    // --- stage positions (last timestep) ---
    for (int j = threadIdx.x; j < NA; j += THREADS) {
        const float* pp = pos + ((size_t)(j * NB + b) * SEQL + (SEQL - 1)) * 2;
        ps[j] = make_float2(pp[0], pp[1]);
    }

    // --- stage h_last tile [256][128] (float4 loads, coalesced 512B rows) ---
    #pragma unroll
    for (int t = threadIdx.x; t < NA * (HID / 4); t += THREADS) {
        const int j = t >> 5;
        const int c = t & 31;
        const float4* src =
            (const float4*)(hidden + ((size_t)(j * NB + b) * SEQL + (SEQL - 1)) * HID) + c;
        ((float4*)hs)[t] = *src;
    }
    __syncthreads();

    const float r  = *radius_ptr;
    const float r2 = r * r;

    const int warp = threadIdx.x >> 5;
    const int lane = threadIdx.x & 31;

    #pragma unroll
    for (int ii = warp; ii < I_PER_BLOCK; ii += NWARPS) {
        const int i = ihalf * I_PER_BLOCK + ii;
        const float2 pi = ps[i];

        unsigned long long a01 = 0ull, a23 = 0ull;   // packed f32x2 accumulators
        int cnt = 0;

        #pragma unroll
        for (int jb = 0; jb < NA; jb += 32) {
            const int j = jb + lane;
            const float2 pj = ps[j];
            const float dx = pi.x - pj.x;
            const float dy = pi.y - pj.y;
            const bool ok = (dx * dx + dy * dy <= r2) && (j != i);
            unsigned m = __ballot_sync(0xffffffffu, ok);
            cnt += __popc(m);

            if (m) {
                int bit = __ffs(m) - 1;
                m &= m - 1;
                ulonglong2 hv =
                    ((const ulonglong2*)(hs + (jb + bit) * HID))[lane];
                while (m) {
                    const int nb = __ffs(m) - 1;
                    m &= m - 1;
                    ulonglong2 nx =
                        ((const ulonglong2*)(hs + (jb + nb) * HID))[lane];
                    addx2(a01, hv.x);
                    addx2(a23, hv.y);
                    hv = nx;
                }
                addx2(a01, hv.x);
                addx2(a23, hv.y);
            }
        }

        const float scale = 1.0f / fmaxf((float)cnt, 1.0f);
        float2 v01 = *(float2*)&a01;
        float2 v23 = *(float2*)&a23;
        float4 o;
        o.x = v01.x * scale; o.y = v01.y * scale;
        o.z = v23.x * scale; o.w = v23.y * scale;
        ((float4*)(out + ((size_t)i * NB + b) * HID))[lane] = o;
    }
}

extern "C" void kernel_launch(void* const* d_in, const int* in_sizes, int n_in,
                              void* d_out, int out_size)
{
    const float* hidden = (const float*)d_in[0];   // (256,64,20,128) f32
    const float* pos    = (const float*)d_in[1];   // (256,64,20,2)  f32
    const float* radius = (const float*)d_in[2];   // scalar f32
    float* out = (float*)d_out;                    // (256,64,128)   f32

    cudaFuncSetAttribute(social_pool_kernel,
                         cudaFuncAttributeMaxDynamicSharedMemorySize,
                         SMEM_BYTES);

    social_pool_kernel<<<NB * 2, THREADS, SMEM_BYTES>>>(hidden, pos, radius, out);
}

// round 3
// speedup vs baseline: 1.2786x; 1.0173x over previous
#include <cuda_runtime.h>
#include <cuda_bf16.h>
#include <cstdint>

// XLSTM social pooling (N=256 agents, B=64, H=128, last timestep only):
// out[i,b,:] = mean over j!=i with ||p_i-p_j||<=r of h_last[j,b,:]
//
// R2 changes vs R1 (18.9us, latency-bound: occ 23%, issue 37%):
//  - 1024 threads/block (32 warps/SM instead of 16) -> hide LDS latency
//  - packed add.rn.f32x2 accumulate (2 instr/neighbor instead of 4 FFMA)
//  - 1-deep software pipeline in the neighbor bit loop (prefetch next row)

#define NA   256
#define NB   64
#define SEQL 20
#define HID  128

#define I_PER_BLOCK 128          // 2 blocks per batch
#define THREADS     1024         // 32 warps -> 4 agents per warp
#define NWARPS      (THREADS / 32)
#define SMEM_BYTES  (NA * HID * 4 + NA * 8)

__device__ __forceinline__ void addx2(unsigned long long& acc, unsigned long long v) {
    asm("add.rn.f32x2 %0, %1, %2;" : "=l"(acc) : "l"(acc), "l"(v));
}

__global__ __launch_bounds__(THREADS, 1)
void social_pool_kernel(const float* __restrict__ hidden,
                        const float* __restrict__ pos,
                        const float* __restrict__ radius_ptr,
                        float* __restrict__ out)
{
    extern __shared__ float smem[];
    float*  hs = smem;                          // [256][128] f32
    float2* ps = (float2*)(smem + NA * HID);    // [256]

    const int b     = blockIdx.x >> 1;
    const int ihalf = blockIdx.x & 1;

    // --- stage positions (last timestep) ---
    for (int j = threadIdx.x; j < NA; j += THREADS) {
        const float* pp = pos + ((size_t)(j * NB + b) * SEQL + (SEQL - 1)) * 2;
        ps[j] = make_float2(pp[0], pp[1]);
    }

    // --- stage h_last tile [256][128] (float4 loads, coalesced 512B rows) ---
    #pragma unroll
    for (int t = threadIdx.x; t < NA * (HID / 4); t += THREADS) {
        const int j = t >> 5;
        const int c = t & 31;
        const float4* src =
            (const float4*)(hidden + ((size_t)(j * NB + b) * SEQL + (SEQL - 1)) * HID) + c;
        ((float4*)hs)[t] = *src;
    }
    __syncthreads();

    const float r  = *radius_ptr;
    const float r2 = r * r;

    const int warp = threadIdx.x >> 5;
    const int lane = threadIdx.x & 31;

    #pragma unroll
    for (int ii = warp; ii < I_PER_BLOCK; ii += NWARPS) {
        const int i = ihalf * I_PER_BLOCK + ii;
        const float2 pi = ps[i];

        unsigned long long a01 = 0ull, a23 = 0ull;   // packed f32x2 accumulators
        int cnt = 0;

        #pragma unroll
        for (int jb = 0; jb < NA; jb += 32) {
            const int j = jb + lane;
            const float2 pj = ps[j];
            const float dx = pi.x - pj.x;
            const float dy = pi.y - pj.y;
            const bool ok = (dx * dx + dy * dy <= r2) && (j != i);
            unsigned m = __ballot_sync(0xffffffffu, ok);
            cnt += __popc(m);

            if (m) {
                int bit = __ffs(m) - 1;
                m &= m - 1;
                ulonglong2 hv =
                    ((const ulonglong2*)(hs + (jb + bit) * HID))[lane];
                while (m) {
                    const int nb = __ffs(m) - 1;
                    m &= m - 1;
                    ulonglong2 nx =
                        ((const ulonglong2*)(hs + (jb + nb) * HID))[lane];
                    addx2(a01, hv.x);
                    addx2(a23, hv.y);
                    hv = nx;
                }
                addx2(a01, hv.x);
                addx2(a23, hv.y);
            }
        }

        const float scale = 1.0f / fmaxf((float)cnt, 1.0f);
        float2 v01 = *(float2*)&a01;
        float2 v23 = *(float2*)&a23;
        float4 o;
        o.x = v01.x * scale; o.y = v01.y * scale;
        o.z = v23.x * scale; o.w = v23.y * scale;
        ((float4*)(out + ((size_t)i * NB + b) * HID))[lane] = o;
    }
}

extern "C" void kernel_launch(void* const* d_in, const int* in_sizes, int n_in,
                              void* d_out, int out_size)
{
    const float* hidden = (const float*)d_in[0];   // (256,64,20,128) f32
    const float* pos    = (const float*)d_in[1];   // (256,64,20,2)  f32
    const float* radius = (const float*)d_in[2];   // scalar f32
    float* out = (float*)d_out;                    // (256,64,128)   f32

    cudaFuncSetAttribute(social_pool_kernel,
                         cudaFuncAttributeMaxDynamicSharedMemorySize,
                         SMEM_BYTES);

    social_pool_kernel<<<NB * 2, THREADS, SMEM_BYTES>>>(hidden, pos, radius, out);
}